// round 2
// baseline (speedup 1.0000x reference)
#include <cuda_runtime.h>
#include <math_constants.h>

// Problem constants (fixed shapes from reference)
#define N_PIX   16384      // B*H*W = 16*32*32
#define K_CODES 8192
#define D_DIM   256

// ---------------- scratch (no allocations allowed) ----------------
__device__ float g_x2[N_PIX];
__device__ float g_c2[K_CODES];
__device__ unsigned long long g_argmin[N_PIX];
__device__ float g_rowmax[N_PIX];
__device__ float g_rowsum[N_PIX];

// ---------------- packed fp32x2 FMA (Blackwell) ----------------
// d.x += ax*bx ; d.y += ay*by   (rounding identical to scalar FFMA)
__device__ __forceinline__ void ffma2(float2& d, float ax, float ay, float bx, float by) {
    asm("{\n\t"
        ".reg .b64 ra, rb, rd;\n\t"
        "mov.b64 ra, {%2, %3};\n\t"
        "mov.b64 rb, {%4, %5};\n\t"
        "mov.b64 rd, {%0, %1};\n\t"
        "fma.rn.f32x2 rd, ra, rb, rd;\n\t"
        "mov.b64 {%0, %1}, rd;\n\t"
        "}"
        : "+f"(d.x), "+f"(d.y)
        : "f"(ax), "f"(ay), "f"(bx), "f"(by));
}

// ---------------- row-norm kernel: one warp per row of length 256 ----------------
__global__ void k_rownorm(const float* __restrict__ src, int nrows, int which) {
    float* dst = which ? g_c2 : g_x2;
    int warp = (blockIdx.x * blockDim.x + threadIdx.x) >> 5;
    int lane = threadIdx.x & 31;
    if (warp >= nrows) return;
    const float* p = src + (size_t)warp * D_DIM;
    float s = 0.f;
#pragma unroll
    for (int i = 0; i < D_DIM; i += 32) {
        float v = p[i + lane];
        s = fmaf(v, v, s);
    }
#pragma unroll
    for (int o = 16; o > 0; o >>= 1) s += __shfl_xor_sync(0xffffffffu, s, o);
    if (lane == 0) dst[warp] = s;
}

__global__ void k_init_argmin() {
    int i = blockIdx.x * blockDim.x + threadIdx.x;
    if (i < N_PIX) g_argmin[i] = 0xFFFFFFFFFFFFFFFFULL;
}

// ---------------- K1: distances GEMM + logit epilogue + argmin ----------------
// C[128 rows x 128 codes] tile = x[128,256] . codebook[128,256]^T (K-major both)
__global__ __launch_bounds__(256, 2)
void k1_dist(const float* __restrict__ x, const float* __restrict__ cb,
             const float* __restrict__ noise, float* __restrict__ logits) {
    __shared__ float As[8][128];
    __shared__ float Bs[8][128];
    __shared__ unsigned long long sMin[128];

    const int tid = threadIdx.x;
    const int tx = tid & 15, ty = tid >> 4;
    const int rowBase = blockIdx.y << 7;
    const int colBase = blockIdx.x << 7;

    if (tid < 128) sMin[tid] = 0xFFFFFFFFFFFFFFFFULL;

    float2 U[4][4], V[4][4];
#pragma unroll
    for (int p = 0; p < 4; p++)
#pragma unroll
        for (int q = 0; q < 4; q++) { U[p][q] = make_float2(0.f, 0.f); V[p][q] = make_float2(0.f, 0.f); }

    const int lr = tid >> 1;
    const int lh = (tid & 1) << 2;
    const float* xg = x  + (size_t)(rowBase + lr) * D_DIM + lh;
    const float* cg = cb + (size_t)(colBase + lr) * D_DIM + lh;

    for (int d0 = 0; d0 < D_DIM; d0 += 8) {
        float4 av = *(const float4*)(xg + d0);
        float4 bv = *(const float4*)(cg + d0);
        __syncthreads();
        As[lh + 0][lr] = av.x; As[lh + 1][lr] = av.y; As[lh + 2][lr] = av.z; As[lh + 3][lr] = av.w;
        Bs[lh + 0][lr] = bv.x; Bs[lh + 1][lr] = bv.y; Bs[lh + 2][lr] = bv.z; Bs[lh + 3][lr] = bv.w;
        __syncthreads();
#pragma unroll
        for (int kk = 0; kk < 8; kk++) {
            float4 a0 = *(const float4*)&As[kk][ty << 3];
            float4 a1 = *(const float4*)&As[kk][(ty << 3) + 4];
            float4 b0 = *(const float4*)&Bs[kk][tx << 3];
            float4 b1 = *(const float4*)&Bs[kk][(tx << 3) + 4];
            float a[8] = {a0.x, a0.y, a0.z, a0.w, a1.x, a1.y, a1.z, a1.w};
            float b[8] = {b0.x, b0.y, b0.z, b0.w, b1.x, b1.y, b1.z, b1.w};
#pragma unroll
            for (int p = 0; p < 4; p++)
#pragma unroll
                for (int q = 0; q < 4; q++) {
                    ffma2(U[p][q], a[2*p], a[2*p+1], b[2*q],   b[2*q+1]);
                    ffma2(V[p][q], a[2*p], a[2*p+1], b[2*q+1], b[2*q]);
                }
        }
    }

    float c2v[8];
#pragma unroll
    for (int j = 0; j < 8; j++) c2v[j] = g_c2[colBase + (tx << 3) + j];

#pragma unroll
    for (int i = 0; i < 8; i++) {
        const int r = rowBase + (ty << 3) + i;
        const float x2v = g_x2[r];
        const float4* np = (const float4*)(noise + (size_t)r * K_CODES + colBase + (tx << 3));
        float4 n0 = np[0], n1 = np[1];
        float nn[8] = {n0.x, n0.y, n0.z, n0.w, n1.x, n1.y, n1.z, n1.w};
        float out[8];
        unsigned long long best = 0xFFFFFFFFFFFFFFFFULL;
#pragma unroll
        for (int j = 0; j < 8; j++) {
            const int p = i >> 1, q = j >> 1;
            float xc;
            if ((i & 1) == 0) xc = ((j & 1) == 0) ? U[p][q].x : V[p][q].x;
            else              xc = ((j & 1) == 0) ? V[p][q].y : U[p][q].y;
            float dist = x2v - 2.0f * xc + c2v[j];
            out[j] = nn[j] - dist;   // logit = (-dist + noise)/tau, tau=1
            unsigned long long pk = ((unsigned long long)__float_as_uint(dist) << 32)
                                    | (unsigned)(colBase + (tx << 3) + j);
            best = best < pk ? best : pk;
        }
        float4* lp = (float4*)(logits + (size_t)r * K_CODES + colBase + (tx << 3));
        lp[0] = make_float4(out[0], out[1], out[2], out[3]);
        lp[1] = make_float4(out[4], out[5], out[6], out[7]);
        atomicMin(&sMin[(ty << 3) + i], best);
    }
    __syncthreads();
    if (tid < 128) atomicMin(&g_argmin[rowBase + tid], sMin[tid]);
}

// ---------------- K2: per-row online softmax stats ----------------
__global__ __launch_bounds__(256)
void k2_stats(const float* __restrict__ logits) {
    const int row = blockIdx.x;
    const float* p = logits + (size_t)row * K_CODES;
    const int t = threadIdx.x;
    float m = -CUDART_INF_F, s = 0.f;
    for (int c = t; c < K_CODES; c += 256) {
        float l = p[c];
        float mn = fmaxf(m, l);
        s = s * __expf(m - mn) + __expf(l - mn);
        m = mn;
    }
    __shared__ float sm[256], ss[256];
    sm[t] = m; ss[t] = s;
    __syncthreads();
    for (int o = 128; o > 0; o >>= 1) {
        if (t < o) {
            float m2 = sm[t + o], s2 = ss[t + o];
            float mn = fmaxf(sm[t], m2);
            ss[t] = ss[t] * __expf(sm[t] - mn) + s2 * __expf(m2 - mn);
            sm[t] = mn;
        }
        __syncthreads();
    }
    if (t == 0) { g_rowmax[row] = sm[0]; g_rowsum[row] = ss[0]; }
}

// ---------------- K3: normalize logits -> encodings (in place) ----------------
__global__ __launch_bounds__(256)
void k3_norm(float* __restrict__ logits) {
    size_t i = (size_t)blockIdx.x * blockDim.x + threadIdx.x;  // float4 index
    const int row = (int)(i >> 11);                            // 2048 float4 per row
    const float m = g_rowmax[row];
    const float inv = 1.0f / g_rowsum[row];
    float4 v = ((float4*)logits)[i];
    v.x = __expf(v.x - m) * inv;
    v.y = __expf(v.y - m) * inv;
    v.z = __expf(v.z - m) * inv;
    v.w = __expf(v.w - m) * inv;
    ((float4*)logits)[i] = v;
}

// ---------------- K4: quantized = encodings @ codebook ----------------
// C[128 rows x 128 d] tile = enc[128, 8192] . codebook[8192, 256] slice
__global__ __launch_bounds__(256, 2)
void k4_quant(const float* __restrict__ enc, const float* __restrict__ cb,
              float* __restrict__ outq) {
    __shared__ float As[8][128];
    __shared__ float Bs[8][128];

    const int tid = threadIdx.x;
    const int tx = tid & 15, ty = tid >> 4;
    const int rowBase = blockIdx.y << 7;
    const int dBase = blockIdx.x << 7;

    float2 U[4][4], V[4][4];
#pragma unroll
    for (int p = 0; p < 4; p++)
#pragma unroll
        for (int q = 0; q < 4; q++) { U[p][q] = make_float2(0.f, 0.f); V[p][q] = make_float2(0.f, 0.f); }

    const int lr = tid >> 1;
    const int lh = (tid & 1) << 2;
    const int bk = tid >> 5;
    const int bl = tid & 31;
    const float* ag = enc + (size_t)(rowBase + lr) * K_CODES + lh;
    const float* bg = cb + (size_t)bk * D_DIM + dBase + (bl << 2);

    for (int k0 = 0; k0 < K_CODES; k0 += 8) {
        float4 av = *(const float4*)(ag + k0);
        float4 bv = *(const float4*)(bg + (size_t)k0 * D_DIM);
        __syncthreads();
        As[lh + 0][lr] = av.x; As[lh + 1][lr] = av.y; As[lh + 2][lr] = av.z; As[lh + 3][lr] = av.w;
        *(float4*)&Bs[bk][bl << 2] = bv;
        __syncthreads();
#pragma unroll
        for (int kk = 0; kk < 8; kk++) {
            float4 a0 = *(const float4*)&As[kk][ty << 3];
            float4 a1 = *(const float4*)&As[kk][(ty << 3) + 4];
            float4 b0 = *(const float4*)&Bs[kk][tx << 3];
            float4 b1 = *(const float4*)&Bs[kk][(tx << 3) + 4];
            float a[8] = {a0.x, a0.y, a0.z, a0.w, a1.x, a1.y, a1.z, a1.w};
            float b[8] = {b0.x, b0.y, b0.z, b0.w, b1.x, b1.y, b1.z, b1.w};
#pragma unroll
            for (int p = 0; p < 4; p++)
#pragma unroll
                for (int q = 0; q < 4; q++) {
                    ffma2(U[p][q], a[2*p], a[2*p+1], b[2*q],   b[2*q+1]);
                    ffma2(V[p][q], a[2*p], a[2*p+1], b[2*q+1], b[2*q]);
                }
        }
    }

#pragma unroll
    for (int i = 0; i < 8; i++) {
        const int r = rowBase + (ty << 3) + i;
        float out[8];
#pragma unroll
        for (int j = 0; j < 8; j++) {
            const int p = i >> 1, q = j >> 1;
            if ((i & 1) == 0) out[j] = ((j & 1) == 0) ? U[p][q].x : V[p][q].x;
            else              out[j] = ((j & 1) == 0) ? V[p][q].y : U[p][q].y;
        }
        float4* op = (float4*)(outq + (size_t)r * D_DIM + dBase + (tx << 3));
        op[0] = make_float4(out[0], out[1], out[2], out[3]);
        op[1] = make_float4(out[4], out[5], out[6], out[7]);
    }
}

// ---------------- K5: indices ----------------
__global__ void k5_idx(float* __restrict__ out_idx) {
    int i = blockIdx.x * blockDim.x + threadIdx.x;
    if (i < N_PIX) out_idx[i] = (float)(unsigned)(g_argmin[i] & 0xFFFFFFFFULL);
}

// ---------------- launcher ----------------
extern "C" void kernel_launch(void* const* d_in, const int* in_sizes, int n_in,
                              void* d_out, int out_size) {
    const float* x     = (const float*)d_in[0];
    const float* cb    = (const float*)d_in[1];
    const float* noise = (const float*)d_in[2];

    float* out     = (float*)d_out;
    float* out_q   = out;                                   // [16384, 256]
    float* out_enc = out + (size_t)N_PIX * D_DIM;           // [16384, 8192]
    float* out_idx = out_enc + (size_t)N_PIX * K_CODES;     // [16384]

    // row norms (8 warps/block)
    k_rownorm<<<N_PIX / 8, 256>>>(x, N_PIX, 0);
    k_rownorm<<<K_CODES / 8, 256>>>(cb, K_CODES, 1);
    k_init_argmin<<<N_PIX / 256, 256>>>();

    // distances GEMM -> logits (scratch in encodings slot) + argmin
    k1_dist<<<dim3(K_CODES / 128, N_PIX / 128), 256>>>(x, cb, noise, out_enc);

    // softmax stats + normalize
    k2_stats<<<N_PIX, 256>>>(out_enc);
    k3_norm<<<(int)(((size_t)N_PIX * K_CODES / 4) / 256), 256>>>(out_enc);

    // quantized GEMM
    k4_quant<<<dim3(D_DIM / 128, N_PIX / 128), 256>>>(out_enc, cb, out_q);

    // indices
    k5_idx<<<N_PIX / 256, 256>>>(out_idx);
}

// round 3
// speedup vs baseline: 1.0006x; 1.0006x over previous
#include <cuda_runtime.h>
#include <math_constants.h>

// Problem constants (fixed shapes from reference)
#define N_PIX   16384      // B*H*W = 16*32*32
#define K_CODES 8192
#define D_DIM   256

// ---------------- scratch (no allocations allowed) ----------------
__device__ float g_x2[N_PIX];
__device__ float g_c2[K_CODES];
__device__ unsigned long long g_argmin[N_PIX];
__device__ float g_rowmax[N_PIX];
__device__ float g_rowsum[N_PIX];

// ---------------- packed fp32x2 FMA (Blackwell) ----------------
// d.x += ax*bx ; d.y += ay*by   (rounding identical to scalar FFMA)
__device__ __forceinline__ void ffma2(float2& d, float ax, float ay, float bx, float by) {
    asm("{\n\t"
        ".reg .b64 ra, rb, rd;\n\t"
        "mov.b64 ra, {%2, %3};\n\t"
        "mov.b64 rb, {%4, %5};\n\t"
        "mov.b64 rd, {%0, %1};\n\t"
        "fma.rn.f32x2 rd, ra, rb, rd;\n\t"
        "mov.b64 {%0, %1}, rd;\n\t"
        "}"
        : "+f"(d.x), "+f"(d.y)
        : "f"(ax), "f"(ay), "f"(bx), "f"(by));
}

// ---------------- row-norm kernel: one warp per row of length 256 ----------------
__global__ void k_rownorm(const float* __restrict__ src, int nrows, int which) {
    float* dst = which ? g_c2 : g_x2;
    int warp = (blockIdx.x * blockDim.x + threadIdx.x) >> 5;
    int lane = threadIdx.x & 31;
    if (warp >= nrows) return;
    const float* p = src + (size_t)warp * D_DIM;
    float s = 0.f;
#pragma unroll
    for (int i = 0; i < D_DIM; i += 32) {
        float v = p[i + lane];
        s = fmaf(v, v, s);
    }
#pragma unroll
    for (int o = 16; o > 0; o >>= 1) s += __shfl_xor_sync(0xffffffffu, s, o);
    if (lane == 0) dst[warp] = s;
}

__global__ void k_init_argmin() {
    int i = blockIdx.x * blockDim.x + threadIdx.x;
    if (i < N_PIX) g_argmin[i] = 0xFFFFFFFFFFFFFFFFULL;
}

// ---------------- K1: distances GEMM + logit epilogue + argmin ----------------
// C[128 rows x 128 codes] tile = x[128,256] . codebook[128,256]^T (K-major both)
__global__ __launch_bounds__(256, 2)
void k1_dist(const float* __restrict__ x, const float* __restrict__ cb,
             const float* __restrict__ noise, float* __restrict__ logits) {
    __shared__ float As[8][128];
    __shared__ float Bs[8][128];
    __shared__ unsigned long long sMin[128];

    const int tid = threadIdx.x;
    const int tx = tid & 15, ty = tid >> 4;
    const int rowBase = blockIdx.y << 7;
    const int colBase = blockIdx.x << 7;

    if (tid < 128) sMin[tid] = 0xFFFFFFFFFFFFFFFFULL;

    float2 U[4][4], V[4][4];
#pragma unroll
    for (int p = 0; p < 4; p++)
#pragma unroll
        for (int q = 0; q < 4; q++) { U[p][q] = make_float2(0.f, 0.f); V[p][q] = make_float2(0.f, 0.f); }

    const int lr = tid >> 1;
    const int lh = (tid & 1) << 2;
    const float* xg = x  + (size_t)(rowBase + lr) * D_DIM + lh;
    const float* cg = cb + (size_t)(colBase + lr) * D_DIM + lh;

    for (int d0 = 0; d0 < D_DIM; d0 += 8) {
        float4 av = *(const float4*)(xg + d0);
        float4 bv = *(const float4*)(cg + d0);
        __syncthreads();
        As[lh + 0][lr] = av.x; As[lh + 1][lr] = av.y; As[lh + 2][lr] = av.z; As[lh + 3][lr] = av.w;
        Bs[lh + 0][lr] = bv.x; Bs[lh + 1][lr] = bv.y; Bs[lh + 2][lr] = bv.z; Bs[lh + 3][lr] = bv.w;
        __syncthreads();
#pragma unroll
        for (int kk = 0; kk < 8; kk++) {
            float4 a0 = *(const float4*)&As[kk][ty << 3];
            float4 a1 = *(const float4*)&As[kk][(ty << 3) + 4];
            float4 b0 = *(const float4*)&Bs[kk][tx << 3];
            float4 b1 = *(const float4*)&Bs[kk][(tx << 3) + 4];
            float a[8] = {a0.x, a0.y, a0.z, a0.w, a1.x, a1.y, a1.z, a1.w};
            float b[8] = {b0.x, b0.y, b0.z, b0.w, b1.x, b1.y, b1.z, b1.w};
#pragma unroll
            for (int p = 0; p < 4; p++)
#pragma unroll
                for (int q = 0; q < 4; q++) {
                    ffma2(U[p][q], a[2*p], a[2*p+1], b[2*q],   b[2*q+1]);
                    ffma2(V[p][q], a[2*p], a[2*p+1], b[2*q+1], b[2*q]);
                }
        }
    }

    float c2v[8];
#pragma unroll
    for (int j = 0; j < 8; j++) c2v[j] = g_c2[colBase + (tx << 3) + j];

#pragma unroll
    for (int i = 0; i < 8; i++) {
        const int r = rowBase + (ty << 3) + i;
        const float x2v = g_x2[r];
        const float4* np = (const float4*)(noise + (size_t)r * K_CODES + colBase + (tx << 3));
        float4 n0 = np[0], n1 = np[1];
        float nn[8] = {n0.x, n0.y, n0.z, n0.w, n1.x, n1.y, n1.z, n1.w};
        float out[8];
        unsigned long long best = 0xFFFFFFFFFFFFFFFFULL;
#pragma unroll
        for (int j = 0; j < 8; j++) {
            const int p = i >> 1, q = j >> 1;
            float xc;
            if ((i & 1) == 0) xc = ((j & 1) == 0) ? U[p][q].x : V[p][q].x;
            else              xc = ((j & 1) == 0) ? V[p][q].y : U[p][q].y;
            float dist = x2v - 2.0f * xc + c2v[j];
            out[j] = nn[j] - dist;   // logit = (-dist + noise)/tau, tau=1
            unsigned long long pk = ((unsigned long long)__float_as_uint(dist) << 32)
                                    | (unsigned)(colBase + (tx << 3) + j);
            best = best < pk ? best : pk;
        }
        float4* lp = (float4*)(logits + (size_t)r * K_CODES + colBase + (tx << 3));
        lp[0] = make_float4(out[0], out[1], out[2], out[3]);
        lp[1] = make_float4(out[4], out[5], out[6], out[7]);
        atomicMin(&sMin[(ty << 3) + i], best);
    }
    __syncthreads();
    if (tid < 128) atomicMin(&g_argmin[rowBase + tid], sMin[tid]);
}

// ---------------- K2: per-row online softmax stats ----------------
__global__ __launch_bounds__(256)
void k2_stats(const float* __restrict__ logits) {
    const int row = blockIdx.x;
    const float* p = logits + (size_t)row * K_CODES;
    const int t = threadIdx.x;
    float m = -CUDART_INF_F, s = 0.f;
    for (int c = t; c < K_CODES; c += 256) {
        float l = p[c];
        float mn = fmaxf(m, l);
        s = s * __expf(m - mn) + __expf(l - mn);
        m = mn;
    }
    __shared__ float sm[256], ss[256];
    sm[t] = m; ss[t] = s;
    __syncthreads();
    for (int o = 128; o > 0; o >>= 1) {
        if (t < o) {
            float m2 = sm[t + o], s2 = ss[t + o];
            float mn = fmaxf(sm[t], m2);
            ss[t] = ss[t] * __expf(sm[t] - mn) + s2 * __expf(m2 - mn);
            sm[t] = mn;
        }
        __syncthreads();
    }
    if (t == 0) { g_rowmax[row] = sm[0]; g_rowsum[row] = ss[0]; }
}

// ---------------- K3: normalize logits -> encodings (in place) ----------------
__global__ __launch_bounds__(256)
void k3_norm(float* __restrict__ logits) {
    size_t i = (size_t)blockIdx.x * blockDim.x + threadIdx.x;  // float4 index
    const int row = (int)(i >> 11);                            // 2048 float4 per row
    const float m = g_rowmax[row];
    const float inv = 1.0f / g_rowsum[row];
    float4 v = ((float4*)logits)[i];
    v.x = __expf(v.x - m) * inv;
    v.y = __expf(v.y - m) * inv;
    v.z = __expf(v.z - m) * inv;
    v.w = __expf(v.w - m) * inv;
    ((float4*)logits)[i] = v;
}

// ---------------- K4: quantized = encodings @ codebook ----------------
// C[128 rows x 128 d] tile = enc[128, 8192] . codebook[8192, 256] slice
__global__ __launch_bounds__(256, 2)
void k4_quant(const float* __restrict__ enc, const float* __restrict__ cb,
              float* __restrict__ outq) {
    __shared__ float As[8][128];
    __shared__ float Bs[8][128];

    const int tid = threadIdx.x;
    const int tx = tid & 15, ty = tid >> 4;
    const int rowBase = blockIdx.y << 7;
    const int dBase = blockIdx.x << 7;

    float2 U[4][4], V[4][4];
#pragma unroll
    for (int p = 0; p < 4; p++)
#pragma unroll
        for (int q = 0; q < 4; q++) { U[p][q] = make_float2(0.f, 0.f); V[p][q] = make_float2(0.f, 0.f); }

    const int lr = tid >> 1;
    const int lh = (tid & 1) << 2;
    const int bk = tid >> 5;
    const int bl = tid & 31;
    const float* ag = enc + (size_t)(rowBase + lr) * K_CODES + lh;
    const float* bg = cb + (size_t)bk * D_DIM + dBase + (bl << 2);

    for (int k0 = 0; k0 < K_CODES; k0 += 8) {
        float4 av = *(const float4*)(ag + k0);
        float4 bv = *(const float4*)(bg + (size_t)k0 * D_DIM);
        __syncthreads();
        As[lh + 0][lr] = av.x; As[lh + 1][lr] = av.y; As[lh + 2][lr] = av.z; As[lh + 3][lr] = av.w;
        *(float4*)&Bs[bk][bl << 2] = bv;
        __syncthreads();
#pragma unroll
        for (int kk = 0; kk < 8; kk++) {
            float4 a0 = *(const float4*)&As[kk][ty << 3];
            float4 a1 = *(const float4*)&As[kk][(ty << 3) + 4];
            float4 b0 = *(const float4*)&Bs[kk][tx << 3];
            float4 b1 = *(const float4*)&Bs[kk][(tx << 3) + 4];
            float a[8] = {a0.x, a0.y, a0.z, a0.w, a1.x, a1.y, a1.z, a1.w};
            float b[8] = {b0.x, b0.y, b0.z, b0.w, b1.x, b1.y, b1.z, b1.w};
#pragma unroll
            for (int p = 0; p < 4; p++)
#pragma unroll
                for (int q = 0; q < 4; q++) {
                    ffma2(U[p][q], a[2*p], a[2*p+1], b[2*q],   b[2*q+1]);
                    ffma2(V[p][q], a[2*p], a[2*p+1], b[2*q+1], b[2*q]);
                }
        }
    }

#pragma unroll
    for (int i = 0; i < 8; i++) {
        const int r = rowBase + (ty << 3) + i;
        float out[8];
#pragma unroll
        for (int j = 0; j < 8; j++) {
            const int p = i >> 1, q = j >> 1;
            if ((i & 1) == 0) out[j] = ((j & 1) == 0) ? U[p][q].x : V[p][q].x;
            else              out[j] = ((j & 1) == 0) ? V[p][q].y : U[p][q].y;
        }
        float4* op = (float4*)(outq + (size_t)r * D_DIM + dBase + (tx << 3));
        op[0] = make_float4(out[0], out[1], out[2], out[3]);
        op[1] = make_float4(out[4], out[5], out[6], out[7]);
    }
}

// ---------------- K5: indices ----------------
__global__ void k5_idx(float* __restrict__ out_idx) {
    int i = blockIdx.x * blockDim.x + threadIdx.x;
    if (i < N_PIX) out_idx[i] = (float)(unsigned)(g_argmin[i] & 0xFFFFFFFFULL);
}

// ---------------- launcher ----------------
extern "C" void kernel_launch(void* const* d_in, const int* in_sizes, int n_in,
                              void* d_out, int out_size) {
    const float* x     = (const float*)d_in[0];
    const float* cb    = (const float*)d_in[1];
    const float* noise = (const float*)d_in[2];

    float* out     = (float*)d_out;
    float* out_q   = out;                                   // [16384, 256]
    float* out_enc = out + (size_t)N_PIX * D_DIM;           // [16384, 8192]
    float* out_idx = out_enc + (size_t)N_PIX * K_CODES;     // [16384]

    // row norms (8 warps/block)
    k_rownorm<<<N_PIX / 8, 256>>>(x, N_PIX, 0);
    k_rownorm<<<K_CODES / 8, 256>>>(cb, K_CODES, 1);
    k_init_argmin<<<N_PIX / 256, 256>>>();

    // distances GEMM -> logits (scratch in encodings slot) + argmin
    k1_dist<<<dim3(K_CODES / 128, N_PIX / 128), 256>>>(x, cb, noise, out_enc);

    // softmax stats + normalize
    k2_stats<<<N_PIX, 256>>>(out_enc);
    k3_norm<<<(int)(((size_t)N_PIX * K_CODES / 4) / 256), 256>>>(out_enc);

    // quantized GEMM
    k4_quant<<<dim3(D_DIM / 128, N_PIX / 128), 256>>>(out_enc, cb, out_q);

    // indices
    k5_idx<<<N_PIX / 256, 256>>>(out_idx);
}

// round 6
// speedup vs baseline: 1.6869x; 1.6859x over previous
#include <cuda_runtime.h>
#include <cuda_fp16.h>
#include <math_constants.h>
#include <cstdint>

#define N_PIX   16384
#define K_CODES 8192
#define D_DIM   256

// ---------------- scratch ----------------
__device__ float g_x2[N_PIX];
__device__ float g_c2[K_CODES];
__device__ unsigned long long g_argmin[N_PIX];
__device__ float g_rowmax[N_PIX];
__device__ float g_rowsum[N_PIX];
__device__ __half g_xs[2][N_PIX * D_DIM];                 // x hi/lo fp16
__device__ __half g_cs[2][K_CODES * D_DIM];               // cb hi/lo fp16
__device__ __half g_cbT[2][(size_t)D_DIM * K_CODES];      // cbT hi/lo fp16
__device__ __half g_enc[2][(size_t)N_PIX * K_CODES];      // encodings hi/lo fp16

__constant__ int c_asel[3] = {0, 0, 1};
__constant__ int c_bsel[3] = {0, 1, 0};

// ---------------- PTX helpers (plain sm_80+) ----------------
__device__ __forceinline__ uint32_t smem_u32(const void* p) {
    uint32_t a;
    asm("{ .reg .u64 t; cvta.to.shared.u64 t, %1; cvt.u32.u64 %0, t; }" : "=r"(a) : "l"(p));
    return a;
}
#define CP16(sa, ga)  asm volatile("cp.async.cg.shared.global [%0], [%1], 16;" :: "r"(sa), "l"(ga) : "memory")
#define CPCOMMIT()    asm volatile("cp.async.commit_group;" ::: "memory")
#define CPWAIT1()     asm volatile("cp.async.wait_group 1;" ::: "memory")
#define CPWAIT0()     asm volatile("cp.async.wait_group 0;" ::: "memory")

#define LDSM4(r0, r1, r2, r3, a) asm volatile(                                   \
    "ldmatrix.sync.aligned.m8n8.x4.shared.b16 {%0,%1,%2,%3}, [%4];"              \
    : "=r"(r0), "=r"(r1), "=r"(r2), "=r"(r3) : "r"(a))

#define MMA(c, a, b) asm volatile(                                               \
    "mma.sync.aligned.m16n8k16.row.col.f32.f16.f16.f32 "                         \
    "{%0,%1,%2,%3}, {%4,%5,%6,%7}, {%8,%9}, {%0,%1,%2,%3};"                      \
    : "+f"((c)[0]), "+f"((c)[1]), "+f"((c)[2]), "+f"((c)[3])                     \
    : "r"((a)[0]), "r"((a)[1]), "r"((a)[2]), "r"((a)[3]),                        \
      "r"((b)[0]), "r"((b)[1]))

// smem tile: 128 rows x 32 fp16, padded row stride 80 bytes -> conflict-free ldmatrix
#define ROWB 80

__device__ __forceinline__ void load_stage(uint32_t sA, uint32_t sB,
                                           const __half* gA, const __half* gB,
                                           int tid, size_t strideA, size_t strideB) {
    const int r = tid >> 1, h = tid & 1;
    uint32_t sa = sA + (uint32_t)(r * ROWB + h * 32);
    const __half* ga = gA + (size_t)r * strideA + h * 16;
    CP16(sa, ga); CP16(sa + 16, ga + 8);
    uint32_t sb = sB + (uint32_t)(r * ROWB + h * 32);
    const __half* gb = gB + (size_t)r * strideB + h * 16;
    CP16(sb, gb); CP16(sb + 16, gb + 8);
    CPCOMMIT();
}

// one K=32 chunk of the 128x128 block tile: warp (wm,wn) computes 64x32
__device__ __forceinline__ void mma_tile(float (&acc)[4][4][4], uint32_t Ab, uint32_t Bb,
                                         int lane, int wm, int wn) {
#pragma unroll
    for (int kk = 0; kk < 2; kk++) {
        uint32_t af[4][4], bf[4][2];
#pragma unroll
        for (int mt = 0; mt < 4; mt++) {
            uint32_t a = Ab + (uint32_t)((wm * 64 + mt * 16 + (lane & 15)) * ROWB
                                         + ((lane >> 4) << 4) + kk * 32);
            LDSM4(af[mt][0], af[mt][1], af[mt][2], af[mt][3], a);
        }
#pragma unroll
        for (int n2 = 0; n2 < 2; n2++) {
            uint32_t a = Bb + (uint32_t)((wn * 32 + n2 * 16 + (lane & 7) + ((lane >> 4) << 3)) * ROWB
                                         + (((lane >> 3) & 1) << 4) + kk * 32);
            LDSM4(bf[2*n2][0], bf[2*n2][1], bf[2*n2+1][0], bf[2*n2+1][1], a);
        }
#pragma unroll
        for (int mt = 0; mt < 4; mt++)
#pragma unroll
            for (int nt = 0; nt < 4; nt++)
                MMA(acc[mt][nt], af[mt], bf[nt]);
    }
}

// ---------------- preprocessing ----------------
__device__ __forceinline__ void split2(float f, __half& h, __half& m) {
    h = __float2half_rn(f);
    m = __float2half_rn(f - __half2float(h));
}

__global__ void k_split(const float* __restrict__ src, int which) {
    int i = blockIdx.x * blockDim.x + threadIdx.x;  // float4 idx
    float4 v = ((const float4*)src)[i];
    float vv[4] = {v.x, v.y, v.z, v.w};
    __half hh[4], mm[4];
#pragma unroll
    for (int t = 0; t < 4; t++) split2(vv[t], hh[t], mm[t]);
    __half2* H = (__half2*)(which ? g_cs[0] : g_xs[0]);
    __half2* M = (__half2*)(which ? g_cs[1] : g_xs[1]);
    H[2*i]   = __halves2half2(hh[0], hh[1]);
    H[2*i+1] = __halves2half2(hh[2], hh[3]);
    M[2*i]   = __halves2half2(mm[0], mm[1]);
    M[2*i+1] = __halves2half2(mm[2], mm[3]);
}

__global__ void k_transpose(const float* __restrict__ cb) {
    __shared__ float t[32][33];
    int k0 = blockIdx.x * 32, d0 = blockIdx.y * 32;
    int tx = threadIdx.x, ty = threadIdx.y;  // 32x8
#pragma unroll
    for (int i = 0; i < 32; i += 8)
        t[ty + i][tx] = cb[(size_t)(k0 + ty + i) * D_DIM + d0 + tx];
    __syncthreads();
#pragma unroll
    for (int i = 0; i < 32; i += 8) {
        float f = t[tx][ty + i];
        __half h, m;
        split2(f, h, m);
        size_t o = (size_t)(d0 + ty + i) * K_CODES + k0 + tx;
        g_cbT[0][o] = h;
        g_cbT[1][o] = m;
    }
}

__global__ void k_rownorm(const float* __restrict__ src, int nrows, int which) {
    float* dst = which ? g_c2 : g_x2;
    int warp = (blockIdx.x * blockDim.x + threadIdx.x) >> 5;
    int lane = threadIdx.x & 31;
    if (warp >= nrows) return;
    const float* p = src + (size_t)warp * D_DIM;
    float s = 0.f;
#pragma unroll
    for (int i = 0; i < D_DIM; i += 32) {
        float v = p[i + lane];
        s = fmaf(v, v, s);
    }
#pragma unroll
    for (int o = 16; o > 0; o >>= 1) s += __shfl_xor_sync(0xffffffffu, s, o);
    if (lane == 0) dst[warp] = s;
}

__global__ void k_init_argmin() {
    int i = blockIdx.x * blockDim.x + threadIdx.x;
    if (i < N_PIX) g_argmin[i] = 0xFFFFFFFFFFFFFFFFULL;
}

// ---------------- GEMM1: x.cbT (3-pass fp16 split) + dist/logit/argmin ----------------
__global__ __launch_bounds__(256, 2)
void k_gemm1(const float* __restrict__ noise, float* __restrict__ logits) {
    __shared__ __align__(16) __half sA[2][128 * 40];
    __shared__ __align__(16) __half sB[2][128 * 40];
    __shared__ float x2s[128], c2s[128];
    __shared__ unsigned long long sMin[128];

    const int tid = threadIdx.x, lane = tid & 31, wid = tid >> 5;
    const int wm = wid >> 2, wn = wid & 3;
    const int rowBase = blockIdx.y << 7, colBase = blockIdx.x << 7;

    if (tid < 128) {
        x2s[tid] = g_x2[rowBase + tid];
        c2s[tid] = g_c2[colBase + tid];
        sMin[tid] = 0xFFFFFFFFFFFFFFFFULL;
    }

    float acc[4][4][4];
#pragma unroll
    for (int a = 0; a < 4; a++)
#pragma unroll
        for (int b = 0; b < 4; b++)
#pragma unroll
            for (int c = 0; c < 4; c++) acc[a][b][c] = 0.f;

    const uint32_t A0 = smem_u32(sA[0]), A1 = smem_u32(sA[1]);
    const uint32_t B0 = smem_u32(sB[0]), B1 = smem_u32(sB[1]);

    load_stage(A0, B0,
               g_xs[0] + (size_t)rowBase * D_DIM,
               g_cs[0] + (size_t)colBase * D_DIM, tid, D_DIM, D_DIM);

    for (int s = 0; s < 24; s++) {   // 3 passes x 8 chunks of K=32
        if (s + 1 < 24) {
            const int pass = (s + 1) >> 3, k0 = ((s + 1) & 7) << 5;
            load_stage((s + 1) & 1 ? A1 : A0, (s + 1) & 1 ? B1 : B0,
                       g_xs[c_asel[pass]] + (size_t)rowBase * D_DIM + k0,
                       g_cs[c_bsel[pass]] + (size_t)colBase * D_DIM + k0,
                       tid, D_DIM, D_DIM);
            CPWAIT1();
        } else {
            CPWAIT0();
        }
        __syncthreads();
        mma_tile(acc, s & 1 ? A1 : A0, s & 1 ? B1 : B0, lane, wm, wn);
        __syncthreads();
    }

    // epilogue: dist = x2 - 2*xc + c2 ; logit = noise - dist ; exact packed argmin
#pragma unroll
    for (int mt = 0; mt < 4; mt++) {
#pragma unroll
        for (int h = 0; h < 2; h++) {
            const int r = wm * 64 + mt * 16 + (lane >> 2) + h * 8;
            const int grow = rowBase + r;
            const float x2v = x2s[r];
            unsigned long long best = 0xFFFFFFFFFFFFFFFFULL;
            const float* nrow = noise + (size_t)grow * K_CODES + colBase;
            float* lrow = logits + (size_t)grow * K_CODES + colBase;
#pragma unroll
            for (int nt = 0; nt < 4; nt++) {
                const int c = wn * 32 + nt * 8 + ((lane & 3) << 1);
                const float xc0 = acc[mt][nt][h * 2 + 0];
                const float xc1 = acc[mt][nt][h * 2 + 1];
                const float d0 = fmaf(-2.f, xc0, x2v) + c2s[c];
                const float d1 = fmaf(-2.f, xc1, x2v) + c2s[c + 1];
                const float2 nz = *(const float2*)(nrow + c);
                *(float2*)(lrow + c) = make_float2(nz.x - d0, nz.y - d1);
                unsigned long long p0 = ((unsigned long long)__float_as_uint(d0) << 32) | (unsigned)(colBase + c);
                unsigned long long p1 = ((unsigned long long)__float_as_uint(d1) << 32) | (unsigned)(colBase + c + 1);
                if (p1 < p0) p0 = p1;
                if (p0 < best) best = p0;
            }
            atomicMin(&sMin[r], best);
        }
    }
    __syncthreads();
    if (tid < 128) atomicMin(&g_argmin[rowBase + tid], sMin[tid]);
}

// ---------------- softmax stats ----------------
__global__ __launch_bounds__(256)
void k2_stats(const float* __restrict__ logits) {
    const int row = blockIdx.x;
    const float* p = logits + (size_t)row * K_CODES;
    const int t = threadIdx.x;
    float m = -CUDART_INF_F, s = 0.f;
    for (int c = t; c < K_CODES; c += 256) {
        float l = p[c];
        float mn = fmaxf(m, l);
        s = s * __expf(m - mn) + __expf(l - mn);
        m = mn;
    }
    __shared__ float sm[256], ss[256];
    sm[t] = m; ss[t] = s;
    __syncthreads();
    for (int o = 128; o > 0; o >>= 1) {
        if (t < o) {
            float m2 = sm[t + o], s2 = ss[t + o];
            float mn = fmaxf(sm[t], m2);
            ss[t] = ss[t] * __expf(sm[t] - mn) + s2 * __expf(m2 - mn);
            sm[t] = mn;
        }
        __syncthreads();
    }
    if (t == 0) { g_rowmax[row] = sm[0]; g_rowsum[row] = ss[0]; }
}

// ---------------- normalize -> f32 encodings + fp16 split copies ----------------
__global__ __launch_bounds__(256)
void k3_norm(float* __restrict__ logits) {
    size_t i = (size_t)blockIdx.x * blockDim.x + threadIdx.x;  // float4 idx
    const int row = (int)(i >> 11);
    const float m = g_rowmax[row];
    const float inv = 1.0f / g_rowsum[row];
    float4 v = ((float4*)logits)[i];
    v.x = __expf(v.x - m) * inv;
    v.y = __expf(v.y - m) * inv;
    v.z = __expf(v.z - m) * inv;
    v.w = __expf(v.w - m) * inv;
    ((float4*)logits)[i] = v;
    float vv[4] = {v.x, v.y, v.z, v.w};
    __half hh[4], mmv[4];
#pragma unroll
    for (int t = 0; t < 4; t++) split2(vv[t], hh[t], mmv[t]);
    __half2* H = (__half2*)g_enc[0];
    __half2* M = (__half2*)g_enc[1];
    H[2*i]   = __halves2half2(hh[0], hh[1]);
    H[2*i+1] = __halves2half2(hh[2], hh[3]);
    M[2*i]   = __halves2half2(mmv[0], mmv[1]);
    M[2*i+1] = __halves2half2(mmv[2], mmv[3]);
}

// ---------------- GEMM2: quantized = enc @ cb (3-pass fp16 split) ----------------
__global__ __launch_bounds__(256, 2)
void k_gemm2(float* __restrict__ outq) {
    __shared__ __align__(16) __half sA[2][128 * 40];
    __shared__ __align__(16) __half sB[2][128 * 40];

    const int tid = threadIdx.x, lane = tid & 31, wid = tid >> 5;
    const int wm = wid >> 2, wn = wid & 3;
    const int rowBase = blockIdx.y << 7, dBase = blockIdx.x << 7;

    float acc[4][4][4];
#pragma unroll
    for (int a = 0; a < 4; a++)
#pragma unroll
        for (int b = 0; b < 4; b++)
#pragma unroll
            for (int c = 0; c < 4; c++) acc[a][b][c] = 0.f;

    const uint32_t A0 = smem_u32(sA[0]), A1 = smem_u32(sA[1]);
    const uint32_t B0 = smem_u32(sB[0]), B1 = smem_u32(sB[1]);

    load_stage(A0, B0,
               g_enc[0] + (size_t)rowBase * K_CODES,
               g_cbT[0] + (size_t)dBase * K_CODES, tid, K_CODES, K_CODES);

    for (int s = 0; s < 768; s++) {   // 3 passes x 256 chunks of K=32
        if (s + 1 < 768) {
            const int pass = (s + 1) >> 8, k0 = ((s + 1) & 255) << 5;
            load_stage((s + 1) & 1 ? A1 : A0, (s + 1) & 1 ? B1 : B0,
                       g_enc[c_asel[pass]] + (size_t)rowBase * K_CODES + k0,
                       g_cbT[c_bsel[pass]] + (size_t)dBase * K_CODES + k0,
                       tid, K_CODES, K_CODES);
            CPWAIT1();
        } else {
            CPWAIT0();
        }
        __syncthreads();
        mma_tile(acc, s & 1 ? A1 : A0, s & 1 ? B1 : B0, lane, wm, wn);
        __syncthreads();
    }

#pragma unroll
    for (int mt = 0; mt < 4; mt++) {
#pragma unroll
        for (int h = 0; h < 2; h++) {
            const int grow = rowBase + wm * 64 + mt * 16 + (lane >> 2) + h * 8;
            float* orow = outq + (size_t)grow * D_DIM + dBase;
#pragma unroll
            for (int nt = 0; nt < 4; nt++) {
                const int c = wn * 32 + nt * 8 + ((lane & 3) << 1);
                *(float2*)(orow + c) = make_float2(acc[mt][nt][h * 2], acc[mt][nt][h * 2 + 1]);
            }
        }
    }
}

// ---------------- indices ----------------
__global__ void k5_idx(float* __restrict__ out_idx) {
    int i = blockIdx.x * blockDim.x + threadIdx.x;
    if (i < N_PIX) out_idx[i] = (float)(unsigned)(g_argmin[i] & 0xFFFFFFFFULL);
}

// ---------------- launcher ----------------
extern "C" void kernel_launch(void* const* d_in, const int* in_sizes, int n_in,
                              void* d_out, int out_size) {
    const float* x     = (const float*)d_in[0];
    const float* cb    = (const float*)d_in[1];
    const float* noise = (const float*)d_in[2];

    float* out     = (float*)d_out;
    float* out_q   = out;                                   // [16384, 256]
    float* out_enc = out + (size_t)N_PIX * D_DIM;           // [16384, 8192]
    float* out_idx = out_enc + (size_t)N_PIX * K_CODES;     // [16384]

    k_split<<<(N_PIX * D_DIM / 4) / 256, 256>>>(x, 0);
    k_split<<<(K_CODES * D_DIM / 4) / 256, 256>>>(cb, 1);
    k_transpose<<<dim3(K_CODES / 32, D_DIM / 32), dim3(32, 8)>>>(cb);
    k_rownorm<<<N_PIX / 8, 256>>>(x, N_PIX, 0);
    k_rownorm<<<K_CODES / 8, 256>>>(cb, K_CODES, 1);
    k_init_argmin<<<N_PIX / 256, 256>>>();

    k_gemm1<<<dim3(K_CODES / 128, N_PIX / 128), 256>>>(noise, out_enc);

    k2_stats<<<N_PIX, 256>>>(out_enc);
    k3_norm<<<(int)(((size_t)N_PIX * K_CODES / 4) / 256), 256>>>(out_enc);

    k_gemm2<<<dim3(D_DIM / 128, N_PIX / 128), 256>>>(out_q);

    k5_idx<<<N_PIX / 256, 256>>>(out_idx);
}

// round 7
// speedup vs baseline: 2.2759x; 1.3491x over previous
#include <cuda_runtime.h>
#include <cuda_fp16.h>
#include <math_constants.h>
#include <cstdint>

#define N_PIX   16384
#define K_CODES 8192
#define D_DIM   256

// ---------------- scratch ----------------
__device__ float g_x2[N_PIX];
__device__ float g_c2[K_CODES];
__device__ unsigned long long g_argmin[N_PIX];
__device__ __half g_xs[2][N_PIX * D_DIM];                 // x hi/lo fp16
__device__ __half g_cs[2][K_CODES * D_DIM];               // cb hi/lo fp16
__device__ __half g_cbT[2][(size_t)D_DIM * K_CODES];      // cbT hi/lo fp16

// ---------------- PTX helpers (plain sm_80+) ----------------
__device__ __forceinline__ uint32_t smem_u32(const void* p) {
    uint32_t a;
    asm("{ .reg .u64 t; cvta.to.shared.u64 t, %1; cvt.u32.u64 %0, t; }" : "=r"(a) : "l"(p));
    return a;
}
#define CP16(sa, ga)  asm volatile("cp.async.cg.shared.global [%0], [%1], 16;" :: "r"(sa), "l"(ga) : "memory")
#define CPCOMMIT()    asm volatile("cp.async.commit_group;" ::: "memory")
#define CPWAIT1()     asm volatile("cp.async.wait_group 1;" ::: "memory")
#define CPWAIT0()     asm volatile("cp.async.wait_group 0;" ::: "memory")

#define LDSM4(r0, r1, r2, r3, a) asm volatile(                                   \
    "ldmatrix.sync.aligned.m8n8.x4.shared.b16 {%0,%1,%2,%3}, [%4];"              \
    : "=r"(r0), "=r"(r1), "=r"(r2), "=r"(r3) : "r"(a))

#define MMA(c, a, b) asm volatile(                                               \
    "mma.sync.aligned.m16n8k16.row.col.f32.f16.f16.f32 "                         \
    "{%0,%1,%2,%3}, {%4,%5,%6,%7}, {%8,%9}, {%0,%1,%2,%3};"                      \
    : "+f"((c)[0]), "+f"((c)[1]), "+f"((c)[2]), "+f"((c)[3])                     \
    : "r"((a)[0]), "r"((a)[1]), "r"((a)[2]), "r"((a)[3]),                        \
      "r"((b)[0]), "r"((b)[1]))

#define ROWB 80          // 128 rows x 32 fp16, row stride 80B (conflict-free ldmatrix)
#define TILEB 10240      // one 128x32 tile

__device__ __forceinline__ uint32_t h2u(__half2 h) { return *reinterpret_cast<uint32_t*>(&h); }
#define STS128(addr, x0, x1, x2, x3) asm volatile("st.shared.v4.b32 [%0], {%1,%2,%3,%4};" \
    :: "r"(addr), "r"(x0), "r"(x1), "r"(x2), "r"(x3) : "memory")

// 3-combo MMA over one K=32 stage: acc += Ah*Bh + Am*Bh + Ah*Bm
__device__ __forceinline__ void mma3_stage(float (&acc)[4][4][4],
                                           uint32_t aH, uint32_t aM, uint32_t bH, uint32_t bM,
                                           int lane, int wm, int wn) {
#pragma unroll
    for (int kk = 0; kk < 2; kk++) {
        uint32_t ah[4][4], am[4][4], bh[4][2], bm[4][2];
#pragma unroll
        for (int mt = 0; mt < 4; mt++) {
            uint32_t off = (uint32_t)((wm * 64 + mt * 16 + (lane & 15)) * ROWB
                                      + ((lane >> 4) << 4) + kk * 32);
            LDSM4(ah[mt][0], ah[mt][1], ah[mt][2], ah[mt][3], aH + off);
            LDSM4(am[mt][0], am[mt][1], am[mt][2], am[mt][3], aM + off);
        }
#pragma unroll
        for (int n2 = 0; n2 < 2; n2++) {
            uint32_t off = (uint32_t)((wn * 32 + n2 * 16 + (lane & 7) + ((lane >> 4) << 3)) * ROWB
                                      + (((lane >> 3) & 1) << 4) + kk * 32);
            LDSM4(bh[2*n2][0], bh[2*n2][1], bh[2*n2+1][0], bh[2*n2+1][1], bH + off);
            LDSM4(bm[2*n2][0], bm[2*n2][1], bm[2*n2+1][0], bm[2*n2+1][1], bM + off);
        }
#pragma unroll
        for (int mt = 0; mt < 4; mt++)
#pragma unroll
            for (int nt = 0; nt < 4; nt++) {
                MMA(acc[mt][nt], ah[mt], bh[nt]);
                MMA(acc[mt][nt], am[mt], bh[nt]);
                MMA(acc[mt][nt], ah[mt], bm[nt]);
            }
    }
}

// ---------------- prepass: fp16 hi/lo split + row norm, one warp per row ----------------
__global__ __launch_bounds__(256)
void k_prep(const float* __restrict__ src, int which) {
    const int row = blockIdx.x * 8 + (threadIdx.x >> 5);
    const int lane = threadIdx.x & 31;
    const float* p = src + (size_t)row * D_DIM + lane * 8;
    float4 v0 = ((const float4*)p)[0], v1 = ((const float4*)p)[1];
    float f[8] = {v0.x, v0.y, v0.z, v0.w, v1.x, v1.y, v1.z, v1.w};
    __half hi[8]; float s = 0.f;
    uint32_t hw[4], mw[4];
#pragma unroll
    for (int t = 0; t < 8; t++) { hi[t] = __float2half_rn(f[t]); s = fmaf(f[t], f[t], s); }
#pragma unroll
    for (int t = 0; t < 4; t++) {
        hw[t] = h2u(__halves2half2(hi[2*t], hi[2*t+1]));
        mw[t] = h2u(__floats2half2_rn(f[2*t]   - __half2float(hi[2*t]),
                                      f[2*t+1] - __half2float(hi[2*t+1])));
    }
    size_t o = ((size_t)row * D_DIM + lane * 8);
    __half* H = which ? g_cs[0] : g_xs[0];
    __half* M = which ? g_cs[1] : g_xs[1];
    *(uint4*)(H + o) = make_uint4(hw[0], hw[1], hw[2], hw[3]);
    *(uint4*)(M + o) = make_uint4(mw[0], mw[1], mw[2], mw[3]);
#pragma unroll
    for (int o2 = 16; o2 > 0; o2 >>= 1) s += __shfl_xor_sync(0xffffffffu, s, o2);
    if (lane == 0) (which ? g_c2 : g_x2)[row] = s;
}

__global__ void k_init_argmin() {
    int i = blockIdx.x * blockDim.x + threadIdx.x;
    if (i < N_PIX) g_argmin[i] = 0xFFFFFFFFFFFFFFFFULL;
}

__global__ void k_transpose(const float* __restrict__ cb) {
    __shared__ float t[32][33];
    int k0 = blockIdx.x * 32, d0 = blockIdx.y * 32;
    int tx = threadIdx.x, ty = threadIdx.y;  // 32x8
#pragma unroll
    for (int i = 0; i < 32; i += 8)
        t[ty + i][tx] = cb[(size_t)(k0 + ty + i) * D_DIM + d0 + tx];
    __syncthreads();
#pragma unroll
    for (int i = 0; i < 32; i += 8) {
        float f = t[tx][ty + i];
        __half h = __float2half_rn(f);
        size_t o = (size_t)(d0 + ty + i) * K_CODES + k0 + tx;
        g_cbT[0][o] = h;
        g_cbT[1][o] = __float2half_rn(f - __half2float(h));
    }
}

// ---------------- GEMM1: x.cbT + dist/logit/argmin, fused 3-combo split ----------------
// dyn smem: 2 stages x [Ah|Am|Bh|Bm] x 10240B = 81920B
__global__ __launch_bounds__(256)
void k_gemm1(const float* __restrict__ noise, float* __restrict__ logits) {
    extern __shared__ __align__(16) char dyn[];
    __shared__ float x2s[128], c2s[128];
    __shared__ unsigned long long sMin[128];
    const uint32_t db = smem_u32(dyn);

    const int tid = threadIdx.x, lane = tid & 31, wid = tid >> 5;
    const int wm = wid >> 2, wn = wid & 3;
    const int rowBase = blockIdx.y << 7, colBase = blockIdx.x << 7;

    if (tid < 128) {
        x2s[tid] = g_x2[rowBase + tid];
        c2s[tid] = g_c2[colBase + tid];
        sMin[tid] = 0xFFFFFFFFFFFFFFFFULL;
    }

    float acc[4][4][4];
#pragma unroll
    for (int a = 0; a < 4; a++)
#pragma unroll
        for (int b = 0; b < 4; b++)
#pragma unroll
            for (int c = 0; c < 4; c++) acc[a][b][c] = 0.f;

    const int r = tid >> 1, h = tid & 1;
    const uint32_t so = (uint32_t)(r * ROWB + h * 32);

    auto load_stage = [&](int s, int k0) {
        uint32_t base = db + s * (4 * TILEB);
        size_t ao = (size_t)(rowBase + r) * D_DIM + k0 + h * 16;
        size_t bo = (size_t)(colBase + r) * D_DIM + k0 + h * 16;
        CP16(base + so, g_xs[0] + ao);                 CP16(base + so + 16, g_xs[0] + ao + 8);
        CP16(base + TILEB + so, g_xs[1] + ao);         CP16(base + TILEB + so + 16, g_xs[1] + ao + 8);
        CP16(base + 2*TILEB + so, g_cs[0] + bo);       CP16(base + 2*TILEB + so + 16, g_cs[0] + bo + 8);
        CP16(base + 3*TILEB + so, g_cs[1] + bo);       CP16(base + 3*TILEB + so + 16, g_cs[1] + bo + 8);
        CPCOMMIT();
    };

    load_stage(0, 0);
    for (int s = 0; s < 8; s++) {
        if (s + 1 < 8) { load_stage((s + 1) & 1, (s + 1) << 5); CPWAIT1(); }
        else           { CPWAIT0(); }
        __syncthreads();
        uint32_t base = db + (s & 1) * (4 * TILEB);
        mma3_stage(acc, base, base + TILEB, base + 2*TILEB, base + 3*TILEB, lane, wm, wn);
        __syncthreads();
    }

    // epilogue: dist = x2 - 2*xc + c2 ; logit = noise - dist ; exact packed argmin
#pragma unroll
    for (int mt = 0; mt < 4; mt++) {
#pragma unroll
        for (int hh = 0; hh < 2; hh++) {
            const int rr = wm * 64 + mt * 16 + (lane >> 2) + hh * 8;
            const int grow = rowBase + rr;
            const float x2v = x2s[rr];
            unsigned long long best = 0xFFFFFFFFFFFFFFFFULL;
            const float* nrow = noise + (size_t)grow * K_CODES + colBase;
            float* lrow = logits + (size_t)grow * K_CODES + colBase;
#pragma unroll
            for (int nt = 0; nt < 4; nt++) {
                const int c = wn * 32 + nt * 8 + ((lane & 3) << 1);
                const float d0 = fmaf(-2.f, acc[mt][nt][hh * 2 + 0], x2v) + c2s[c];
                const float d1 = fmaf(-2.f, acc[mt][nt][hh * 2 + 1], x2v) + c2s[c + 1];
                const float2 nz = *(const float2*)(nrow + c);
                *(float2*)(lrow + c) = make_float2(nz.x - d0, nz.y - d1);
                unsigned long long p0 = ((unsigned long long)__float_as_uint(d0) << 32) | (unsigned)(colBase + c);
                unsigned long long p1 = ((unsigned long long)__float_as_uint(d1) << 32) | (unsigned)(colBase + c + 1);
                if (p1 < p0) p0 = p1;
                if (p0 < best) best = p0;
            }
            atomicMin(&sMin[rr], best);
        }
    }
    __syncthreads();
    if (tid < 128) atomicMin(&g_argmin[rowBase + tid], sMin[tid]);
}

// ---------------- fused softmax: one block per row, row cached in smem ----------------
__global__ __launch_bounds__(256)
void k_softmax(float* __restrict__ logits) {
    __shared__ float buf[K_CODES];
    __shared__ float red[8];
    const int row = blockIdx.x, t = threadIdx.x, lane = t & 31, w = t >> 5;
    float* p = logits + (size_t)row * K_CODES;

    float m = -CUDART_INF_F;
    for (int c = t * 4; c < K_CODES; c += 1024) {
        float4 v = *(const float4*)(p + c);
        *(float4*)(buf + c) = v;
        m = fmaxf(m, fmaxf(fmaxf(v.x, v.y), fmaxf(v.z, v.w)));
    }
#pragma unroll
    for (int o = 16; o > 0; o >>= 1) m = fmaxf(m, __shfl_xor_sync(0xffffffffu, m, o));
    if (lane == 0) red[w] = m;
    __syncthreads();
    m = fmaxf(fmaxf(fmaxf(red[0], red[1]), fmaxf(red[2], red[3])),
              fmaxf(fmaxf(red[4], red[5]), fmaxf(red[6], red[7])));
    __syncthreads();

    float s = 0.f;
    for (int c = t * 4; c < K_CODES; c += 1024) {
        float4 v = *(const float4*)(buf + c);
        v.x = __expf(v.x - m); v.y = __expf(v.y - m);
        v.z = __expf(v.z - m); v.w = __expf(v.w - m);
        *(float4*)(buf + c) = v;
        s += (v.x + v.y) + (v.z + v.w);
    }
#pragma unroll
    for (int o = 16; o > 0; o >>= 1) s += __shfl_xor_sync(0xffffffffu, s, o);
    if (lane == 0) red[w] = s;
    __syncthreads();
    const float inv = 1.0f / (((red[0] + red[1]) + (red[2] + red[3]))
                            + ((red[4] + red[5]) + (red[6] + red[7])));
    for (int c = t * 4; c < K_CODES; c += 1024) {
        float4 v = *(const float4*)(buf + c);
        v.x *= inv; v.y *= inv; v.z *= inv; v.w *= inv;
        *(float4*)(p + c) = v;
    }
}

// ---------------- GEMM2: quantized = enc(f32, split on the fly) @ cbT ----------------
// dyn smem: [Ah|Am] + 2 stages x [Bh|Bm] = 6*10240 = 61440B
__global__ __launch_bounds__(256)
void k_gemm2(const float* __restrict__ enc, float* __restrict__ outq) {
    extern __shared__ __align__(16) char dyn[];
    const uint32_t db = smem_u32(dyn);
    const uint32_t aH = db, aM = db + TILEB;

    const int tid = threadIdx.x, lane = tid & 31, wid = tid >> 5;
    const int wm = wid >> 2, wn = wid & 3;
    const int rowBase = blockIdx.y << 7, dBase = blockIdx.x << 7;

    float acc[4][4][4];
#pragma unroll
    for (int a = 0; a < 4; a++)
#pragma unroll
        for (int b = 0; b < 4; b++)
#pragma unroll
            for (int c = 0; c < 4; c++) acc[a][b][c] = 0.f;

    const int r = tid >> 1, h = tid & 1;
    const uint32_t so = (uint32_t)(r * ROWB + h * 32);
    const float* arow = enc + (size_t)(rowBase + r) * K_CODES + h * 16;

    auto loadB = [&](int s, int k0) {
        uint32_t base = db + 2 * TILEB + s * (2 * TILEB);
        size_t bo = (size_t)(dBase + r) * K_CODES + k0 + h * 16;
        CP16(base + so, g_cbT[0] + bo);         CP16(base + so + 16, g_cbT[0] + bo + 8);
        CP16(base + TILEB + so, g_cbT[1] + bo); CP16(base + TILEB + so + 16, g_cbT[1] + bo + 8);
        CPCOMMIT();
    };

    float4 a0 = ((const float4*)arow)[0], a1 = ((const float4*)arow)[1];
    float4 a2 = ((const float4*)arow)[2], a3 = ((const float4*)arow)[3];
    loadB(0, 0);

    for (int s = 0; s < 256; s++) {
        // convert current A regs -> smem hi/lo
        float f[16] = {a0.x, a0.y, a0.z, a0.w, a1.x, a1.y, a1.z, a1.w,
                       a2.x, a2.y, a2.z, a2.w, a3.x, a3.y, a3.z, a3.w};
        uint32_t hw[8], mw[8];
#pragma unroll
        for (int t = 0; t < 8; t++) {
            __half h0 = __float2half_rn(f[2*t]), h1 = __float2half_rn(f[2*t+1]);
            hw[t] = h2u(__halves2half2(h0, h1));
            mw[t] = h2u(__floats2half2_rn(f[2*t]   - __half2float(h0),
                                          f[2*t+1] - __half2float(h1)));
        }
        STS128(aH + so,      hw[0], hw[1], hw[2], hw[3]);
        STS128(aH + so + 16, hw[4], hw[5], hw[6], hw[7]);
        STS128(aM + so,      mw[0], mw[1], mw[2], mw[3]);
        STS128(aM + so + 16, mw[4], mw[5], mw[6], mw[7]);

        if (s + 1 < 256) {
            const float* an = arow + ((s + 1) << 5);
            a0 = ((const float4*)an)[0]; a1 = ((const float4*)an)[1];
            a2 = ((const float4*)an)[2]; a3 = ((const float4*)an)[3];
            loadB((s + 1) & 1, (s + 1) << 5);
            CPWAIT1();
        } else {
            CPWAIT0();
        }
        __syncthreads();
        uint32_t bbase = db + 2 * TILEB + (s & 1) * (2 * TILEB);
        mma3_stage(acc, aH, aM, bbase, bbase + TILEB, lane, wm, wn);
        __syncthreads();
    }

#pragma unroll
    for (int mt = 0; mt < 4; mt++) {
#pragma unroll
        for (int hh = 0; hh < 2; hh++) {
            const int grow = rowBase + wm * 64 + mt * 16 + (lane >> 2) + hh * 8;
            float* orow = outq + (size_t)grow * D_DIM + dBase;
#pragma unroll
            for (int nt = 0; nt < 4; nt++) {
                const int c = wn * 32 + nt * 8 + ((lane & 3) << 1);
                *(float2*)(orow + c) = make_float2(acc[mt][nt][hh * 2], acc[mt][nt][hh * 2 + 1]);
            }
        }
    }
}

// ---------------- indices ----------------
__global__ void k5_idx(float* __restrict__ out_idx) {
    int i = blockIdx.x * blockDim.x + threadIdx.x;
    if (i < N_PIX) out_idx[i] = (float)(unsigned)(g_argmin[i] & 0xFFFFFFFFULL);
}

// ---------------- launcher ----------------
extern "C" void kernel_launch(void* const* d_in, const int* in_sizes, int n_in,
                              void* d_out, int out_size) {
    const float* x     = (const float*)d_in[0];
    const float* cb    = (const float*)d_in[1];
    const float* noise = (const float*)d_in[2];

    float* out     = (float*)d_out;
    float* out_q   = out;                                   // [16384, 256]
    float* out_enc = out + (size_t)N_PIX * D_DIM;           // [16384, 8192]
    float* out_idx = out_enc + (size_t)N_PIX * K_CODES;     // [16384]

    static bool attr_done = false;
    if (!attr_done) {
        cudaFuncSetAttribute(k_gemm1, cudaFuncAttributeMaxDynamicSharedMemorySize, 81920);
        cudaFuncSetAttribute(k_gemm2, cudaFuncAttributeMaxDynamicSharedMemorySize, 61440);
        attr_done = true;
    }

    k_prep<<<N_PIX / 8, 256>>>(x, 0);                                   // 1
    k_prep<<<K_CODES / 8, 256>>>(cb, 1);                                // 2
    k_init_argmin<<<N_PIX / 256, 256>>>();                              // 3
    k_gemm1<<<dim3(K_CODES / 128, N_PIX / 128), 256, 81920>>>(noise, out_enc);  // 4 (ncu slot)
    k_transpose<<<dim3(K_CODES / 32, D_DIM / 32), dim3(32, 8)>>>(cb);   // 5
    k_softmax<<<N_PIX, 256>>>(out_enc);                                 // 6
    k_gemm2<<<dim3(D_DIM / 128, N_PIX / 128), 256, 61440>>>(out_enc, out_q);    // 7
    k5_idx<<<N_PIX / 256, 256>>>(out_idx);                              // 8
}

// round 8
// speedup vs baseline: 2.7658x; 1.2153x over previous
#include <cuda_runtime.h>
#include <cuda_fp16.h>
#include <math_constants.h>
#include <cstdint>

#define N_PIX   16384
#define K_CODES 8192
#define D_DIM   256

// ---------------- scratch ----------------
__device__ float g_x2[N_PIX];
__device__ float g_c2[K_CODES];
__device__ unsigned long long g_argmin[N_PIX];
__device__ __half g_xs[2][N_PIX * D_DIM];                 // x hi/lo fp16
__device__ __half g_cs[2][K_CODES * D_DIM];               // cb hi/lo fp16
__device__ __half g_cbT[(size_t)D_DIM * K_CODES];         // cbT hi fp16
__device__ __half g_ench[(size_t)N_PIX * K_CODES];        // encodings hi fp16

// ---------------- PTX helpers (plain sm_80+) ----------------
__device__ __forceinline__ uint32_t smem_u32(const void* p) {
    uint32_t a;
    asm("{ .reg .u64 t; cvta.to.shared.u64 t, %1; cvt.u32.u64 %0, t; }" : "=r"(a) : "l"(p));
    return a;
}
#define CP16(sa, ga)  asm volatile("cp.async.cg.shared.global [%0], [%1], 16;" :: "r"(sa), "l"(ga) : "memory")
#define CPCOMMIT()    asm volatile("cp.async.commit_group;" ::: "memory")
#define CPWAIT1()     asm volatile("cp.async.wait_group 1;" ::: "memory")
#define CPWAIT0()     asm volatile("cp.async.wait_group 0;" ::: "memory")
#define PREF_L2(ga)   asm volatile("prefetch.global.L2 [%0];" :: "l"(ga))

#define LDSM4(r0, r1, r2, r3, a) asm volatile(                                   \
    "ldmatrix.sync.aligned.m8n8.x4.shared.b16 {%0,%1,%2,%3}, [%4];"              \
    : "=r"(r0), "=r"(r1), "=r"(r2), "=r"(r3) : "r"(a))

#define MMA(c, a, b) asm volatile(                                               \
    "mma.sync.aligned.m16n8k16.row.col.f32.f16.f16.f32 "                         \
    "{%0,%1,%2,%3}, {%4,%5,%6,%7}, {%8,%9}, {%0,%1,%2,%3};"                      \
    : "+f"((c)[0]), "+f"((c)[1]), "+f"((c)[2]), "+f"((c)[3])                     \
    : "r"((a)[0]), "r"((a)[1]), "r"((a)[2]), "r"((a)[3]),                        \
      "r"((b)[0]), "r"((b)[1]))

#define ROWB 80          // 128 rows x 32 fp16, stride 80B (conflict-free ldmatrix)
#define TILEB 10240      // one 128x32 fp16 tile
#define ROWB2 144        // 128 rows x 64 fp16, stride 144B
#define TILE2 18432      // one 128x64 fp16 tile

__device__ __forceinline__ uint32_t h2u(__half2 h) { return *reinterpret_cast<uint32_t*>(&h); }

// 3-combo MMA over one K=32 stage: acc += Ah*Bh + Am*Bh + Ah*Bm
__device__ __forceinline__ void mma3_stage(float (&acc)[4][4][4],
                                           uint32_t aH, uint32_t aM, uint32_t bH, uint32_t bM,
                                           int lane, int wm, int wn) {
#pragma unroll
    for (int kk = 0; kk < 2; kk++) {
        uint32_t ah[4][4], am[4][4], bh[4][2], bm[4][2];
#pragma unroll
        for (int mt = 0; mt < 4; mt++) {
            uint32_t off = (uint32_t)((wm * 64 + mt * 16 + (lane & 15)) * ROWB
                                      + ((lane >> 4) << 4) + kk * 32);
            LDSM4(ah[mt][0], ah[mt][1], ah[mt][2], ah[mt][3], aH + off);
            LDSM4(am[mt][0], am[mt][1], am[mt][2], am[mt][3], aM + off);
        }
#pragma unroll
        for (int n2 = 0; n2 < 2; n2++) {
            uint32_t off = (uint32_t)((wn * 32 + n2 * 16 + (lane & 7) + ((lane >> 4) << 3)) * ROWB
                                      + (((lane >> 3) & 1) << 4) + kk * 32);
            LDSM4(bh[2*n2][0], bh[2*n2][1], bh[2*n2+1][0], bh[2*n2+1][1], bH + off);
            LDSM4(bm[2*n2][0], bm[2*n2][1], bm[2*n2+1][0], bm[2*n2+1][1], bM + off);
        }
#pragma unroll
        for (int mt = 0; mt < 4; mt++)
#pragma unroll
            for (int nt = 0; nt < 4; nt++) {
                MMA(acc[mt][nt], ah[mt], bh[nt]);
                MMA(acc[mt][nt], am[mt], bh[nt]);
                MMA(acc[mt][nt], ah[mt], bm[nt]);
            }
    }
}

// single-combo MMA over one K=64 stage (stride ROWB2)
__device__ __forceinline__ void mma1_stage(float (&acc)[4][4][4], uint32_t aB, uint32_t bB,
                                           int lane, int wm, int wn) {
#pragma unroll
    for (int kk = 0; kk < 4; kk++) {
        uint32_t af[4][4], bf[4][2];
#pragma unroll
        for (int mt = 0; mt < 4; mt++) {
            uint32_t off = (uint32_t)((wm * 64 + mt * 16 + (lane & 15)) * ROWB2
                                      + ((lane >> 4) << 4) + kk * 32);
            LDSM4(af[mt][0], af[mt][1], af[mt][2], af[mt][3], aB + off);
        }
#pragma unroll
        for (int n2 = 0; n2 < 2; n2++) {
            uint32_t off = (uint32_t)((wn * 32 + n2 * 16 + (lane & 7) + ((lane >> 4) << 3)) * ROWB2
                                      + (((lane >> 3) & 1) << 4) + kk * 32);
            LDSM4(bf[2*n2][0], bf[2*n2][1], bf[2*n2+1][0], bf[2*n2+1][1], bB + off);
        }
#pragma unroll
        for (int mt = 0; mt < 4; mt++)
#pragma unroll
            for (int nt = 0; nt < 4; nt++)
                MMA(acc[mt][nt], af[mt], bf[nt]);
    }
}

// ---------------- prepass: fp16 hi/lo split + row norm, one warp per row ----------------
__global__ __launch_bounds__(256)
void k_prep(const float* __restrict__ src, int which) {
    const int row = blockIdx.x * 8 + (threadIdx.x >> 5);
    const int lane = threadIdx.x & 31;
    const float* p = src + (size_t)row * D_DIM + lane * 8;
    float4 v0 = ((const float4*)p)[0], v1 = ((const float4*)p)[1];
    float f[8] = {v0.x, v0.y, v0.z, v0.w, v1.x, v1.y, v1.z, v1.w};
    __half hi[8]; float s = 0.f;
    uint32_t hw[4], mw[4];
#pragma unroll
    for (int t = 0; t < 8; t++) { hi[t] = __float2half_rn(f[t]); s = fmaf(f[t], f[t], s); }
#pragma unroll
    for (int t = 0; t < 4; t++) {
        hw[t] = h2u(__halves2half2(hi[2*t], hi[2*t+1]));
        mw[t] = h2u(__floats2half2_rn(f[2*t]   - __half2float(hi[2*t]),
                                      f[2*t+1] - __half2float(hi[2*t+1])));
    }
    size_t o = ((size_t)row * D_DIM + lane * 8);
    __half* H = which ? g_cs[0] : g_xs[0];
    __half* M = which ? g_cs[1] : g_xs[1];
    *(uint4*)(H + o) = make_uint4(hw[0], hw[1], hw[2], hw[3]);
    *(uint4*)(M + o) = make_uint4(mw[0], mw[1], mw[2], mw[3]);
#pragma unroll
    for (int o2 = 16; o2 > 0; o2 >>= 1) s += __shfl_xor_sync(0xffffffffu, s, o2);
    if (lane == 0) (which ? g_c2 : g_x2)[row] = s;
}

__global__ void k_init_argmin() {
    int i = blockIdx.x * blockDim.x + threadIdx.x;
    if (i < N_PIX) g_argmin[i] = 0xFFFFFFFFFFFFFFFFULL;
}

__global__ void k_transpose(const float* __restrict__ cb) {
    __shared__ float t[32][33];
    int k0 = blockIdx.x * 32, d0 = blockIdx.y * 32;
    int tx = threadIdx.x, ty = threadIdx.y;  // 32x8
#pragma unroll
    for (int i = 0; i < 32; i += 8)
        t[ty + i][tx] = cb[(size_t)(k0 + ty + i) * D_DIM + d0 + tx];
    __syncthreads();
#pragma unroll
    for (int i = 0; i < 32; i += 8)
        g_cbT[(size_t)(d0 + ty + i) * K_CODES + k0 + tx] = __float2half_rn(t[tx][ty + i]);
}

// ---------------- GEMM1: x.cbT + dist/logit/argmin, fused 3-combo split ----------------
// dyn smem: 2 stages x [Ah|Am|Bh|Bm] x 10240B = 81920B
__global__ __launch_bounds__(256)
void k_gemm1(const float* __restrict__ noise, float* __restrict__ logits) {
    extern __shared__ __align__(16) char dyn[];
    __shared__ float x2s[128], c2s[128];
    __shared__ unsigned long long sMin[128];
    const uint32_t db = smem_u32(dyn);

    const int tid = threadIdx.x, lane = tid & 31, wid = tid >> 5;
    const int wm = wid >> 2, wn = wid & 3;
    const int rowBase = blockIdx.y << 7, colBase = blockIdx.x << 7;

    if (tid < 128) {
        x2s[tid] = g_x2[rowBase + tid];
        c2s[tid] = g_c2[colBase + tid];
        sMin[tid] = 0xFFFFFFFFFFFFFFFFULL;
    }

    float acc[4][4][4];
#pragma unroll
    for (int a = 0; a < 4; a++)
#pragma unroll
        for (int b = 0; b < 4; b++)
#pragma unroll
            for (int c = 0; c < 4; c++) acc[a][b][c] = 0.f;

    const int r = tid >> 1, h = tid & 1;
    const uint32_t so = (uint32_t)(r * ROWB + h * 32);

    auto load_stage = [&](int s, int k0) {
        uint32_t base = db + s * (4 * TILEB);
        size_t ao = (size_t)(rowBase + r) * D_DIM + k0 + h * 16;
        size_t bo = (size_t)(colBase + r) * D_DIM + k0 + h * 16;
        CP16(base + so, g_xs[0] + ao);                 CP16(base + so + 16, g_xs[0] + ao + 8);
        CP16(base + TILEB + so, g_xs[1] + ao);         CP16(base + TILEB + so + 16, g_xs[1] + ao + 8);
        CP16(base + 2*TILEB + so, g_cs[0] + bo);       CP16(base + 2*TILEB + so + 16, g_cs[0] + bo + 8);
        CP16(base + 3*TILEB + so, g_cs[1] + bo);       CP16(base + 3*TILEB + so + 16, g_cs[1] + bo + 8);
        CPCOMMIT();
    };

    load_stage(0, 0);

    // L2-prefetch this CTA's epilogue noise tile (128 rows x 512B = 512 lines of 128B)
    {
        const char* nbase = (const char*)noise + ((size_t)rowBase * K_CODES + colBase) * 4;
#pragma unroll
        for (int t2 = 0; t2 < 2; t2++) {
            int idx = tid + t2 * 256;                    // 0..511
            PREF_L2(nbase + (size_t)(idx >> 2) * (K_CODES * 4) + (idx & 3) * 128);
        }
    }

    for (int s = 0; s < 8; s++) {
        if (s + 1 < 8) { load_stage((s + 1) & 1, (s + 1) << 5); CPWAIT1(); }
        else           { CPWAIT0(); }
        __syncthreads();
        uint32_t base = db + (s & 1) * (4 * TILEB);
        mma3_stage(acc, base, base + TILEB, base + 2*TILEB, base + 3*TILEB, lane, wm, wn);
        __syncthreads();
    }

    // epilogue: dist = x2 - 2*xc + c2 ; logit = noise - dist ; exact packed argmin
#pragma unroll
    for (int mt = 0; mt < 4; mt++) {
#pragma unroll
        for (int hh = 0; hh < 2; hh++) {
            const int rr = wm * 64 + mt * 16 + (lane >> 2) + hh * 8;
            const int grow = rowBase + rr;
            const float x2v = x2s[rr];
            unsigned long long best = 0xFFFFFFFFFFFFFFFFULL;
            const float* nrow = noise + (size_t)grow * K_CODES + colBase;
            float* lrow = logits + (size_t)grow * K_CODES + colBase;
#pragma unroll
            for (int nt = 0; nt < 4; nt++) {
                const int c = wn * 32 + nt * 8 + ((lane & 3) << 1);
                const float d0 = fmaf(-2.f, acc[mt][nt][hh * 2 + 0], x2v) + c2s[c];
                const float d1 = fmaf(-2.f, acc[mt][nt][hh * 2 + 1], x2v) + c2s[c + 1];
                const float2 nz = *(const float2*)(nrow + c);
                *(float2*)(lrow + c) = make_float2(nz.x - d0, nz.y - d1);
                unsigned long long p0 = ((unsigned long long)__float_as_uint(d0) << 32) | (unsigned)(colBase + c);
                unsigned long long p1 = ((unsigned long long)__float_as_uint(d1) << 32) | (unsigned)(colBase + c + 1);
                if (p1 < p0) p0 = p1;
                if (p0 < best) best = p0;
            }
            atomicMin(&sMin[rr], best);
        }
    }
    __syncthreads();
    if (tid < 128) atomicMin(&g_argmin[rowBase + tid], sMin[tid]);
}

// ---------------- fused softmax: one block per row, row cached in smem ----------------
// writes f32 encodings (output) + fp16 enc-hi (for GEMM2)
__global__ __launch_bounds__(256)
void k_softmax(float* __restrict__ logits) {
    __shared__ float buf[K_CODES];
    __shared__ float red[8];
    const int row = blockIdx.x, t = threadIdx.x, lane = t & 31, w = t >> 5;
    float* p = logits + (size_t)row * K_CODES;

    float m = -CUDART_INF_F;
    for (int c = t * 4; c < K_CODES; c += 1024) {
        float4 v = *(const float4*)(p + c);
        *(float4*)(buf + c) = v;
        m = fmaxf(m, fmaxf(fmaxf(v.x, v.y), fmaxf(v.z, v.w)));
    }
#pragma unroll
    for (int o = 16; o > 0; o >>= 1) m = fmaxf(m, __shfl_xor_sync(0xffffffffu, m, o));
    if (lane == 0) red[w] = m;
    __syncthreads();
    m = fmaxf(fmaxf(fmaxf(red[0], red[1]), fmaxf(red[2], red[3])),
              fmaxf(fmaxf(red[4], red[5]), fmaxf(red[6], red[7])));
    __syncthreads();

    float s = 0.f;
    for (int c = t * 4; c < K_CODES; c += 1024) {
        float4 v = *(const float4*)(buf + c);
        v.x = __expf(v.x - m); v.y = __expf(v.y - m);
        v.z = __expf(v.z - m); v.w = __expf(v.w - m);
        *(float4*)(buf + c) = v;
        s += (v.x + v.y) + (v.z + v.w);
    }
#pragma unroll
    for (int o = 16; o > 0; o >>= 1) s += __shfl_xor_sync(0xffffffffu, s, o);
    if (lane == 0) red[w] = s;
    __syncthreads();
    const float inv = 1.0f / (((red[0] + red[1]) + (red[2] + red[3]))
                            + ((red[4] + red[5]) + (red[6] + red[7])));
    for (int c = t * 4; c < K_CODES; c += 1024) {
        float4 v = *(const float4*)(buf + c);
        v.x *= inv; v.y *= inv; v.z *= inv; v.w *= inv;
        *(float4*)(p + c) = v;
        *(uint2*)(g_ench + (size_t)row * K_CODES + c) =
            make_uint2(h2u(__floats2half2_rn(v.x, v.y)), h2u(__floats2half2_rn(v.z, v.w)));
    }
}

// ---------------- GEMM2: quantized = enc_h @ cbT_h (single-combo fp16) ----------------
// dyn smem: 2 stages x [A|B] x 18432B = 73728B ; grid (2, 128) -> one wave at 2 CTAs/SM
__global__ __launch_bounds__(256)
void k_gemm2(float* __restrict__ outq) {
    extern __shared__ __align__(16) char dyn[];
    const uint32_t db = smem_u32(dyn);

    const int tid = threadIdx.x, lane = tid & 31, wid = tid >> 5;
    const int wm = wid >> 2, wn = wid & 3;
    const int rowBase = blockIdx.y << 7, dBase = blockIdx.x << 7;

    float acc[4][4][4];
#pragma unroll
    for (int a = 0; a < 4; a++)
#pragma unroll
        for (int b = 0; b < 4; b++)
#pragma unroll
            for (int c = 0; c < 4; c++) acc[a][b][c] = 0.f;

    const int r = tid >> 1, h = tid & 1;
    const uint32_t so = (uint32_t)(r * ROWB2 + h * 64);

    auto load_stage = [&](int s, int k0) {
        uint32_t base = db + s * (2 * TILE2);
        size_t ao = (size_t)(rowBase + r) * K_CODES + k0 + h * 32;
        size_t bo = (size_t)(dBase + r) * K_CODES + k0 + h * 32;
        CP16(base + so,      g_ench + ao);      CP16(base + so + 16, g_ench + ao + 8);
        CP16(base + so + 32, g_ench + ao + 16); CP16(base + so + 48, g_ench + ao + 24);
        uint32_t bb = base + TILE2;
        CP16(bb + so,      g_cbT + bo);         CP16(bb + so + 16, g_cbT + bo + 8);
        CP16(bb + so + 32, g_cbT + bo + 16);    CP16(bb + so + 48, g_cbT + bo + 24);
        CPCOMMIT();
    };

    load_stage(0, 0);
    for (int s = 0; s < 128; s++) {
        if (s + 1 < 128) { load_stage((s + 1) & 1, (s + 1) << 6); CPWAIT1(); }
        else             { CPWAIT0(); }
        __syncthreads();
        uint32_t base = db + (s & 1) * (2 * TILE2);
        mma1_stage(acc, base, base + TILE2, lane, wm, wn);
        __syncthreads();
    }

#pragma unroll
    for (int mt = 0; mt < 4; mt++) {
#pragma unroll
        for (int hh = 0; hh < 2; hh++) {
            const int grow = rowBase + wm * 64 + mt * 16 + (lane >> 2) + hh * 8;
            float* orow = outq + (size_t)grow * D_DIM + dBase;
#pragma unroll
            for (int nt = 0; nt < 4; nt++) {
                const int c = wn * 32 + nt * 8 + ((lane & 3) << 1);
                *(float2*)(orow + c) = make_float2(acc[mt][nt][hh * 2], acc[mt][nt][hh * 2 + 1]);
            }
        }
    }
}

// ---------------- indices ----------------
__global__ void k5_idx(float* __restrict__ out_idx) {
    int i = blockIdx.x * blockDim.x + threadIdx.x;
    if (i < N_PIX) out_idx[i] = (float)(unsigned)(g_argmin[i] & 0xFFFFFFFFULL);
}

// ---------------- launcher ----------------
extern "C" void kernel_launch(void* const* d_in, const int* in_sizes, int n_in,
                              void* d_out, int out_size) {
    const float* x     = (const float*)d_in[0];
    const float* cb    = (const float*)d_in[1];
    const float* noise = (const float*)d_in[2];

    float* out     = (float*)d_out;
    float* out_q   = out;                                   // [16384, 256]
    float* out_enc = out + (size_t)N_PIX * D_DIM;           // [16384, 8192]
    float* out_idx = out_enc + (size_t)N_PIX * K_CODES;     // [16384]

    static bool attr_done = false;
    if (!attr_done) {
        cudaFuncSetAttribute(k_gemm1, cudaFuncAttributeMaxDynamicSharedMemorySize, 81920);
        cudaFuncSetAttribute(k_gemm2, cudaFuncAttributeMaxDynamicSharedMemorySize, 73728);
        attr_done = true;
    }

    k_prep<<<N_PIX / 8, 256>>>(x, 0);                                   // 1
    k_prep<<<K_CODES / 8, 256>>>(cb, 1);                                // 2
    k_init_argmin<<<N_PIX / 256, 256>>>();                              // 3
    k_gemm1<<<dim3(K_CODES / 128, N_PIX / 128), 256, 81920>>>(noise, out_enc);  // 4 (ncu slot)
    k_transpose<<<dim3(K_CODES / 32, D_DIM / 32), dim3(32, 8)>>>(cb);   // 5
    k_softmax<<<N_PIX, 256>>>(out_enc);                                 // 6
    k_gemm2<<<dim3(D_DIM / 128, N_PIX / 128), 256, 73728>>>(out_q);     // 7
    k5_idx<<<N_PIX / 256, 256>>>(out_idx);                              // 8
}